// round 7
// baseline (speedup 1.0000x reference)
#include <cuda_runtime.h>
#include <stdint.h>

#define NN 262144
#define SCAN_BS 512
#define SCAN_NB 512   // NN / SCAN_BS

// ---------------- device scratch (static, no allocation) ----------------
__device__ int   g_deg[4 * NN];
__device__ int   g_ptr[4][NN + 1];
__device__ int   g_cnt[4][NN];
__device__ int   g_bsum[4][SCAN_NB];
__device__ int   g_src[4][4000000];     // gg needs 4M, others 2M
__device__ float g_wh[2000000];         // reordered hist edge weights
__device__ float g_dinv_gg[NN], g_dinv_ss[NN];
__device__ float g_x8a[NN * 8], g_x8b[NN * 8], g_x8c[NN * 8];  // padded 5->8 dims
__device__ float g_gx[NN * 64];         // game_x
__device__ float g_agg[NN * 64];        // aggregation scratch
__device__ float g_s0[NN * 64], g_s1[NN * 64], g_s2[NN * 64], g_s3[NN * 64];

// ---------------- packed f32x2 helpers (Blackwell FFMA2 via PTX) ----------------
typedef unsigned long long ull;
__device__ __forceinline__ ull pack2(float lo, float hi) {
    ull r; asm("mov.b64 %0, {%1, %2};" : "=l"(r) : "f"(lo), "f"(hi)); return r;
}
__device__ __forceinline__ void unpack2(ull v, float& lo, float& hi) {
    asm("mov.b64 {%0, %1}, %2;" : "=f"(lo), "=f"(hi) : "l"(v));
}
__device__ __forceinline__ ull ffma2(ull a, ull b, ull c) {
    ull d; asm("fma.rn.f32x2 %0, %1, %2, %3;" : "=l"(d) : "l"(a), "l"(b), "l"(c));
    return d;
}

// compile-time buffer pick
__device__ __forceinline__ const float* pick64(int i) {
    switch (i) {
        case 3: return g_gx;
        case 4: return g_agg;
        case 5: return g_s0;
        case 6: return g_s1;
        case 7: return g_s2;
        default: return g_s3;
    }
}
__device__ __forceinline__ float* pick64w(int i) {
    switch (i) {
        case 4: return g_agg;
        case 6: return g_s1;
        case 7: return g_s2;
        default: return g_s3;
    }
}
__device__ __forceinline__ const float* pick8(int i) {
    switch (i) {
        case 0: return g_x8a;
        case 1: return g_x8b;
        default: return g_x8c;
    }
}
__device__ __forceinline__ float* pick8w(int i) {
    switch (i) {
        case 1: return g_x8b;
        default: return g_x8c;
    }
}

// ---------------- CSR build (edges INT32), fused across the 4 graphs ----------------
__global__ void k_zero_deg() {
    int i = blockIdx.x * blockDim.x + threadIdx.x;
    if (i < 4 * NN) g_deg[i] = 0;
}

__global__ void k_count_all(const int* __restrict__ e0, const int* __restrict__ e1,
                            const int* __restrict__ e2, const int* __restrict__ e3,
                            int E0, int E1, int E2, int E3) {
    int i = blockIdx.x * blockDim.x + threadIdx.x;
    int gi, j; const int* ei; int E;
    if (i < E0)                { gi = 0; j = i;                ei = e0; E = E0; }
    else if (i < E0 + E1)      { gi = 1; j = i - E0;           ei = e1; E = E1; }
    else if (i < E0 + E1 + E2) { gi = 2; j = i - E0 - E1;      ei = e2; E = E2; }
    else if (i < E0 + E1 + E2 + E3) { gi = 3; j = i - E0 - E1 - E2; ei = e3; E = E3; }
    else return;
    atomicAdd(&g_deg[gi * NN + ei[E + j]], 1);
}

__global__ void k_scan1() {
    __shared__ int s[SCAN_BS];
    int gi = blockIdx.y;
    int tid = threadIdx.x;
    int i = blockIdx.x * SCAN_BS + tid;
    int v = g_deg[gi * NN + i];
    s[tid] = v;
    __syncthreads();
    for (int off = 1; off < SCAN_BS; off <<= 1) {
        int t = (tid >= off) ? s[tid - off] : 0;
        __syncthreads();
        s[tid] += t;
        __syncthreads();
    }
    g_ptr[gi][i] = s[tid] - v;
    if (tid == SCAN_BS - 1) g_bsum[gi][blockIdx.x] = s[tid];
}

__global__ void k_scan2() {
    __shared__ int s[SCAN_NB];
    int gi = blockIdx.x;
    int tid = threadIdx.x;
    int v = g_bsum[gi][tid];
    s[tid] = v;
    __syncthreads();
    for (int off = 1; off < SCAN_NB; off <<= 1) {
        int t = (tid >= off) ? s[tid - off] : 0;
        __syncthreads();
        s[tid] += t;
        __syncthreads();
    }
    g_bsum[gi][tid] = s[tid] - v;
}

__global__ void k_scan3(int E0, int E1, int E2, int E3) {
    int gi = blockIdx.y;
    int tid = threadIdx.x;
    int i = blockIdx.x * SCAN_BS + tid;
    int v = g_ptr[gi][i] + g_bsum[gi][blockIdx.x];
    g_ptr[gi][i] = v;
    g_cnt[gi][i] = v;
    if (i == 0) g_ptr[gi][NN] = (gi == 0) ? E0 : (gi == 1) ? E1 : (gi == 2) ? E2 : E3;
}

__global__ void k_fill_all(const int* __restrict__ e0, const int* __restrict__ e1,
                           const int* __restrict__ e2, const int* __restrict__ e3,
                           const float* __restrict__ ea,
                           int E0, int E1, int E2, int E3) {
    int i = blockIdx.x * blockDim.x + threadIdx.x;
    int gi, j; const int* ei; int E;
    if (i < E0)                { gi = 0; j = i;                ei = e0; E = E0; }
    else if (i < E0 + E1)      { gi = 1; j = i - E0;           ei = e1; E = E1; }
    else if (i < E0 + E1 + E2) { gi = 2; j = i - E0 - E1;      ei = e2; E = E2; }
    else if (i < E0 + E1 + E2 + E3) { gi = 3; j = i - E0 - E1 - E2; ei = e3; E = E3; }
    else return;
    int r = ei[j];
    int c = ei[E + j];
    int p = atomicAdd(&g_cnt[gi][c], 1);
    g_src[gi][p] = r;
    if (gi == 1) g_wh[p] = ea[j];
}

__global__ void k_dinv() {
    int i = blockIdx.x * blockDim.x + threadIdx.x;
    if (i < NN) {
        int dg = g_ptr[0][i + 1] - g_ptr[0][i];
        g_dinv_gg[i] = (dg > 0) ? rsqrtf((float)dg) : 0.f;
        int ds = g_ptr[3][i + 1] - g_ptr[3][i];
        g_dinv_ss[i] = (ds > 0) ? rsqrtf((float)ds) : 0.f;
    }
}

// ---------------- TAG1 (5-dim, padded to 8) ----------------
__global__ void k_pad(const float* __restrict__ x) {
    int i = blockIdx.x * blockDim.x + threadIdx.x;
    if (i < NN) {
        const float* r = x + (size_t)i * 5;
        size_t o = (size_t)i * 8;
        *(float4*)(g_x8a + o)     = make_float4(r[0], r[1], r[2], r[3]);
        *(float4*)(g_x8a + o + 4) = make_float4(r[4], 0.f, 0.f, 0.f);
    }
}

// one normalized hop in 5-dim space (thread per dst), 4-edge unrolled for MLP
__global__ void k_hop5(int in_i, int out_i) {
    const float* __restrict__ x8 = pick8(in_i);
    float* __restrict__ y8 = pick8w(out_i);
    int d = blockIdx.x * blockDim.x + threadIdx.x;
    if (d >= NN) return;
    int beg = g_ptr[0][d], end = g_ptr[0][d + 1];
    float a0 = 0, a1 = 0, a2 = 0, a3 = 0, a4 = 0;
    int e = beg;
    for (; e + 4 <= end; e += 4) {
        int sA = g_src[0][e], sB = g_src[0][e + 1], sC = g_src[0][e + 2], sD = g_src[0][e + 3];
        float wA = g_dinv_gg[sA], wB = g_dinv_gg[sB], wC = g_dinv_gg[sC], wD = g_dinv_gg[sD];
        float4 vA = *(const float4*)(x8 + (size_t)sA * 8);
        float4 vB = *(const float4*)(x8 + (size_t)sB * 8);
        float4 vC = *(const float4*)(x8 + (size_t)sC * 8);
        float4 vD = *(const float4*)(x8 + (size_t)sD * 8);
        float fA = x8[(size_t)sA * 8 + 4], fB = x8[(size_t)sB * 8 + 4];
        float fC = x8[(size_t)sC * 8 + 4], fD = x8[(size_t)sD * 8 + 4];
        a0 = fmaf(wA, vA.x, a0); a1 = fmaf(wA, vA.y, a1); a2 = fmaf(wA, vA.z, a2);
        a3 = fmaf(wA, vA.w, a3); a4 = fmaf(wA, fA, a4);
        a0 = fmaf(wB, vB.x, a0); a1 = fmaf(wB, vB.y, a1); a2 = fmaf(wB, vB.z, a2);
        a3 = fmaf(wB, vB.w, a3); a4 = fmaf(wB, fB, a4);
        a0 = fmaf(wC, vC.x, a0); a1 = fmaf(wC, vC.y, a1); a2 = fmaf(wC, vC.z, a2);
        a3 = fmaf(wC, vC.w, a3); a4 = fmaf(wC, fC, a4);
        a0 = fmaf(wD, vD.x, a0); a1 = fmaf(wD, vD.y, a1); a2 = fmaf(wD, vD.z, a2);
        a3 = fmaf(wD, vD.w, a3); a4 = fmaf(wD, fD, a4);
    }
    for (; e < end; e++) {
        int s = g_src[0][e];
        float w = g_dinv_gg[s];
        size_t o = (size_t)s * 8;
        float4 v = *(const float4*)(x8 + o);
        float v4 = x8[o + 4];
        a0 = fmaf(w, v.x, a0); a1 = fmaf(w, v.y, a1);
        a2 = fmaf(w, v.z, a2); a3 = fmaf(w, v.w, a3);
        a4 = fmaf(w, v4, a4);
    }
    float sd = g_dinv_gg[d];
    size_t o = (size_t)d * 8;
    *(float4*)(y8 + o)     = make_float4(a0 * sd, a1 * sd, a2 * sd, a3 * sd);
    *(float4*)(y8 + o + 4) = make_float4(a4 * sd, 0.f, 0.f, 0.f);
}

// gx = relu(x8a@W0 + x8b@W1 + x8c@W2 + b); W is (3,5,64)
__global__ void k_tag1(const float* __restrict__ W, const float* __restrict__ b) {
    __shared__ __align__(16) float sW[960];
    __shared__ __align__(16) float sb[64];
    __shared__ __align__(16) float sx[8][16];
    int tid = threadIdx.x;
    for (int i = tid; i < 960; i += 256) sW[i] = W[i];
    if (tid < 64) sb[tid] = b[tid];
    int ni = tid >> 5, tc = tid & 31;
    size_t node = (size_t)blockIdx.x * 8 + ni;
    if (tc < 5)       sx[ni][tc] = g_x8a[node * 8 + tc];
    else if (tc < 10) sx[ni][tc] = g_x8b[node * 8 + (tc - 5)];
    else if (tc < 15) sx[ni][tc] = g_x8c[node * 8 + (tc - 10)];
    __syncthreads();
    int c0 = 2 * tc;
    ull acc = pack2(sb[c0], sb[c0 + 1]);
#pragma unroll
    for (int k = 0; k < 3; k++)
#pragma unroll
        for (int i = 0; i < 5; i++) {
            float xv = sx[ni][k * 5 + i];
            ull w = *(const ull*)&sW[(k * 5 + i) * 64 + c0];
            acc = ffma2(pack2(xv, xv), w, acc);
        }
    float a0, a1; unpack2(acc, a0, a1);
    *(float2*)&g_gx[node * 64 + c0] = make_float2(fmaxf(a0, 0.f), fmaxf(a1, 0.f));
}

// ---------------- 64-dim hop (warp per dst), LDG.64 lanes + 4-edge unroll ----------------
// lane covers cols (2*lane, 2*lane+1). MODE 0: w=g_wh[e]. MODE 1: mean. MODE 2: sym-norm.
template <int MODE>
__global__ void k_hop64(int in_i, int out_i, int gi) {
    const float* __restrict__ x = pick64(in_i);
    float* __restrict__ y = pick64w(out_i);
    int wid = (blockIdx.x * blockDim.x + threadIdx.x) >> 5;
    if (wid >= NN) return;
    int lane = threadIdx.x & 31;
    const int* __restrict__ src = g_src[gi];
    int beg = g_ptr[gi][wid], end = g_ptr[gi][wid + 1];
    ull accA = 0, accB = 0, accC = 0, accD = 0;  // packed f32x2, bits of (0.f,0.f) == 0
    int col = 2 * lane;
    int e = beg;
    for (; e + 4 <= end; e += 4) {
        int sA = src[e], sB = src[e + 1], sC = src[e + 2], sD = src[e + 3];
        float wA, wB, wC, wD;
        if (MODE == 0) { wA = g_wh[e]; wB = g_wh[e + 1]; wC = g_wh[e + 2]; wD = g_wh[e + 3]; }
        else if (MODE == 2) {
            wA = g_dinv_ss[sA]; wB = g_dinv_ss[sB]; wC = g_dinv_ss[sC]; wD = g_dinv_ss[sD];
        } else { wA = wB = wC = wD = 1.f; }
        ull vA = *(const ull*)(x + (size_t)sA * 64 + col);
        ull vB = *(const ull*)(x + (size_t)sB * 64 + col);
        ull vC = *(const ull*)(x + (size_t)sC * 64 + col);
        ull vD = *(const ull*)(x + (size_t)sD * 64 + col);
        accA = ffma2(pack2(wA, wA), vA, accA);
        accB = ffma2(pack2(wB, wB), vB, accB);
        accC = ffma2(pack2(wC, wC), vC, accC);
        accD = ffma2(pack2(wD, wD), vD, accD);
    }
    for (; e < end; e++) {
        int s = src[e];
        float w;
        if (MODE == 0)      w = g_wh[e];
        else if (MODE == 2) w = g_dinv_ss[s];
        else                w = 1.f;
        ull v = *(const ull*)(x + (size_t)s * 64 + col);
        accA = ffma2(pack2(w, w), v, accA);
    }
    float aAx, aAy, aBx, aBy, aCx, aCy, aDx, aDy;
    unpack2(accA, aAx, aAy); unpack2(accB, aBx, aBy);
    unpack2(accC, aCx, aCy); unpack2(accD, aDx, aDy);
    float r0 = (aAx + aBx) + (aCx + aDx);
    float r1 = (aAy + aBy) + (aCy + aDy);
    float sc = 1.f;
    if (MODE == 1) { int c = end - beg; if (c > 0) sc = 1.f / (float)c; }
    if (MODE == 2) sc = g_dinv_ss[wid];
    *(float2*)(y + (size_t)wid * 64 + col) = make_float2(r0 * sc, r1 * sc);
}

// ============ register-blocked combines: 32 nodes/block, 4 nodes x 2 cols/thread ============

__global__ void k_gc(const float* __restrict__ xs, const float* __restrict__ wrel,
                     const float* __restrict__ brel, const float* __restrict__ wroot) {
    __shared__ __align__(16) float sW[4096];
    __shared__ __align__(16) float sWo[384];
    __shared__ __align__(16) float sb[64];
    __shared__ __align__(16) float sx[2048];
    __shared__ __align__(16) float sxs[192];
    int tid = threadIdx.x;
    size_t base = (size_t)blockIdx.x * 2048;
    for (int i = tid; i < 4096; i += 256) sW[i] = wrel[i];
    for (int i = tid; i < 384; i += 256) sWo[i] = wroot[i];
    for (int i = tid; i < 2048; i += 256) sx[i] = g_agg[base + i];
    for (int i = tid; i < 192; i += 256) sxs[i] = xs[(size_t)blockIdx.x * 192 + i];
    if (tid < 64) sb[tid] = brel[tid];
    __syncthreads();
    int tc = tid & 31, g = tid >> 5;
    int c0 = 2 * tc;
    ull bias = pack2(sb[c0], sb[c0 + 1]);
    ull acc0 = bias, acc1 = bias, acc2 = bias, acc3 = bias;
    int nb = g * 4;
#pragma unroll 8
    for (int j = 0; j < 64; j++) {
        ull w = *(const ull*)&sW[j * 64 + c0];
        acc0 = ffma2(pack2(sx[(nb + 0) * 64 + j], sx[(nb + 0) * 64 + j]), w, acc0);
        acc1 = ffma2(pack2(sx[(nb + 1) * 64 + j], sx[(nb + 1) * 64 + j]), w, acc1);
        acc2 = ffma2(pack2(sx[(nb + 2) * 64 + j], sx[(nb + 2) * 64 + j]), w, acc2);
        acc3 = ffma2(pack2(sx[(nb + 3) * 64 + j], sx[(nb + 3) * 64 + j]), w, acc3);
    }
#pragma unroll
    for (int j = 0; j < 6; j++) {
        ull w = *(const ull*)&sWo[j * 64 + c0];
        acc0 = ffma2(pack2(sxs[(nb + 0) * 6 + j], sxs[(nb + 0) * 6 + j]), w, acc0);
        acc1 = ffma2(pack2(sxs[(nb + 1) * 6 + j], sxs[(nb + 1) * 6 + j]), w, acc1);
        acc2 = ffma2(pack2(sxs[(nb + 2) * 6 + j], sxs[(nb + 2) * 6 + j]), w, acc2);
        acc3 = ffma2(pack2(sxs[(nb + 3) * 6 + j], sxs[(nb + 3) * 6 + j]), w, acc3);
    }
    size_t nbase = (size_t)blockIdx.x * 32 + nb;
    ull accs[4] = { acc0, acc1, acc2, acc3 };
#pragma unroll
    for (int m = 0; m < 4; m++) {
        float a0, a1; unpack2(accs[m], a0, a1);
        *(float2*)&g_s0[(nbase + m) * 64 + c0] = make_float2(fmaxf(a0, 0.f), fmaxf(a1, 0.f));
    }
}

__global__ void k_sage(const float* __restrict__ wl, const float* __restrict__ bl,
                       const float* __restrict__ wr) {
    __shared__ __align__(16) float sW[4096];
    __shared__ __align__(16) float sb[64];
    __shared__ __align__(16) float sm[2048];
    __shared__ __align__(16) float ss[2048];
    int tid = threadIdx.x;
    size_t base = (size_t)blockIdx.x * 2048;
    for (int i = tid; i < 2048; i += 256) { sm[i] = g_agg[base + i]; ss[i] = g_s0[base + i]; }
    for (int i = tid; i < 4096; i += 256) sW[i] = wl[i];
    if (tid < 64) sb[tid] = bl[tid];
    __syncthreads();
    int tc = tid & 31, g = tid >> 5;
    int c0 = 2 * tc;
    int nb = g * 4;
    ull bias = pack2(sb[c0], sb[c0 + 1]);
    ull acc0 = bias, acc1 = bias, acc2 = bias, acc3 = bias;
#pragma unroll 8
    for (int j = 0; j < 64; j++) {
        ull w = *(const ull*)&sW[j * 64 + c0];
        acc0 = ffma2(pack2(sm[(nb + 0) * 64 + j], sm[(nb + 0) * 64 + j]), w, acc0);
        acc1 = ffma2(pack2(sm[(nb + 1) * 64 + j], sm[(nb + 1) * 64 + j]), w, acc1);
        acc2 = ffma2(pack2(sm[(nb + 2) * 64 + j], sm[(nb + 2) * 64 + j]), w, acc2);
        acc3 = ffma2(pack2(sm[(nb + 3) * 64 + j], sm[(nb + 3) * 64 + j]), w, acc3);
    }
    __syncthreads();
    for (int i = tid; i < 4096; i += 256) sW[i] = wr[i];
    __syncthreads();
#pragma unroll 8
    for (int j = 0; j < 64; j++) {
        ull w = *(const ull*)&sW[j * 64 + c0];
        acc0 = ffma2(pack2(ss[(nb + 0) * 64 + j], ss[(nb + 0) * 64 + j]), w, acc0);
        acc1 = ffma2(pack2(ss[(nb + 1) * 64 + j], ss[(nb + 1) * 64 + j]), w, acc1);
        acc2 = ffma2(pack2(ss[(nb + 2) * 64 + j], ss[(nb + 2) * 64 + j]), w, acc2);
        acc3 = ffma2(pack2(ss[(nb + 3) * 64 + j], ss[(nb + 3) * 64 + j]), w, acc3);
    }
    size_t nbase = (size_t)blockIdx.x * 32 + nb;
    ull accs[4] = { acc0, acc1, acc2, acc3 };
#pragma unroll
    for (int m = 0; m < 4; m++) {
        float a0, a1; unpack2(accs[m], a0, a1);
        *(float2*)&g_s0[(nbase + m) * 64 + c0] = make_float2(fmaxf(a0, 0.f), fmaxf(a1, 0.f));
    }
}

__global__ void k_tag2(const float* __restrict__ W, const float* __restrict__ b,
                       const float* __restrict__ lw, const float* __restrict__ lb,
                       float* __restrict__ out) {
    __shared__ __align__(16) float sW[4096];
    __shared__ __align__(16) float sx[2048];
    __shared__ __align__(16) float st[2048];
    __shared__ __align__(16) float sLin[512];
    __shared__ __align__(16) float sb[64];
    __shared__ __align__(16) float slb[8];
    int tid = threadIdx.x;
    for (int i = tid; i < 512; i += 256) sLin[i] = lw[i];
    if (tid < 64) sb[tid] = b[tid];
    if (tid < 8) slb[tid] = lb[tid];
    __syncthreads();
    int tc = tid & 31, g = tid >> 5;
    int c0 = 2 * tc;
    int nb = g * 4;
    size_t base = (size_t)blockIdx.x * 2048;
    ull bias = pack2(sb[c0], sb[c0 + 1]);
    ull acc0 = bias, acc1 = bias, acc2 = bias, acc3 = bias;
#pragma unroll
    for (int stage = 0; stage < 4; stage++) {
        __syncthreads();
        const float* Sk = (stage == 0) ? g_s0 : (stage == 1) ? g_s1
                         : (stage == 2) ? g_s2 : g_s3;
        for (int i = tid; i < 2048; i += 256) sx[i] = Sk[base + i];
        for (int i = tid; i < 4096; i += 256) sW[i] = W[stage * 4096 + i];
        __syncthreads();
#pragma unroll 8
        for (int j = 0; j < 64; j++) {
            ull w = *(const ull*)&sW[j * 64 + c0];
            acc0 = ffma2(pack2(sx[(nb + 0) * 64 + j], sx[(nb + 0) * 64 + j]), w, acc0);
            acc1 = ffma2(pack2(sx[(nb + 1) * 64 + j], sx[(nb + 1) * 64 + j]), w, acc1);
            acc2 = ffma2(pack2(sx[(nb + 2) * 64 + j], sx[(nb + 2) * 64 + j]), w, acc2);
            acc3 = ffma2(pack2(sx[(nb + 3) * 64 + j], sx[(nb + 3) * 64 + j]), w, acc3);
        }
    }
    ull accs[4] = { acc0, acc1, acc2, acc3 };
#pragma unroll
    for (int m = 0; m < 4; m++) {
        float a0, a1; unpack2(accs[m], a0, a1);
        st[(nb + m) * 64 + c0]     = fmaxf(a0, 0.f);
        st[(nb + m) * 64 + c0 + 1] = fmaxf(a1, 0.f);
    }
    __syncthreads();
    int n = tid >> 3, o = tid & 7;
    float acc = slb[o];
#pragma unroll 8
    for (int j = 0; j < 64; j++) acc = fmaf(st[n * 64 + j], sLin[j * 8 + o], acc);
    out[((size_t)blockIdx.x * 32 + n) * 8 + o] = acc;
}

// ---------------- host launch (kernel launches ONLY) ----------------
extern "C" void kernel_launch(void* const* d_in, const int* in_sizes, int n_in,
                              void* d_out, int out_size) {
    const float* x_game     = (const float*)d_in[0];
    const float* x_state    = (const float*)d_in[1];
    const int* e_gg         = (const int*)d_in[2];
    const int* e_hist       = (const int*)d_in[3];
    const int* e_in         = (const int*)d_in[4];
    const int* e_ss         = (const int*)d_in[5];
    const float* ea_hist    = (const float*)d_in[6];
    const float* tag1_w     = (const float*)d_in[7];
    const float* tag1_b     = (const float*)d_in[8];
    const float* tag2_w     = (const float*)d_in[9];
    const float* tag2_b     = (const float*)d_in[10];
    const float* gc_w_rel   = (const float*)d_in[11];
    const float* gc_b_rel   = (const float*)d_in[12];
    const float* gc_w_root  = (const float*)d_in[13];
    const float* sage_w_l   = (const float*)d_in[14];
    const float* sage_b_l   = (const float*)d_in[15];
    const float* sage_w_r   = (const float*)d_in[16];
    const float* lin_w      = (const float*)d_in[17];
    const float* lin_b      = (const float*)d_in[18];

    int E0 = in_sizes[2] / 2, E1 = in_sizes[3] / 2, E2 = in_sizes[4] / 2, E3 = in_sizes[5] / 2;
    long long Etot = (long long)E0 + E1 + E2 + E3;

    // ---- CSR build (fused launches) ----
    k_zero_deg<<<(4 * NN + 255) / 256, 256>>>();
    k_count_all<<<(int)((Etot + 255) / 256), 256>>>(e_gg, e_hist, e_in, e_ss, E0, E1, E2, E3);
    {
        dim3 grid1(SCAN_NB, 4);
        k_scan1<<<grid1, SCAN_BS>>>();
        k_scan2<<<4, SCAN_NB>>>();
        k_scan3<<<grid1, SCAN_BS>>>(E0, E1, E2, E3);
    }
    k_fill_all<<<(int)((Etot + 255) / 256), 256>>>(e_gg, e_hist, e_in, e_ss, ea_hist,
                                                   E0, E1, E2, E3);
    k_dinv<<<(NN + 255) / 256, 256>>>();

    // ---- TAGConv1 (game graph, 5-dim propagation) ----
    k_pad<<<(NN + 255) / 256, 256>>>(x_game);
    k_hop5<<<(NN + 255) / 256, 256>>>(0, 1);   // x8a -> x8b
    k_hop5<<<(NN + 255) / 256, 256>>>(1, 2);   // x8b -> x8c
    k_tag1<<<NN / 8, 256>>>(tag1_w, tag1_b);

    // ---- GraphConv (hist, weighted) ----
    k_hop64<0><<<NN / 8, 256>>>(3, 4, 1);      // gx -> agg
    k_gc<<<NN / 32, 256>>>(x_state, gc_w_rel, gc_b_rel, gc_w_root);

    // ---- SAGEConv (in, mean) ----
    k_hop64<1><<<NN / 8, 256>>>(3, 4, 2);      // gx -> agg
    k_sage<<<NN / 32, 256>>>(sage_w_l, sage_b_l, sage_w_r);

    // ---- TAGConv2 (ss, 3 normalized hops) + fused final Linear ----
    k_hop64<2><<<NN / 8, 256>>>(5, 6, 3);      // s0 -> s1
    k_hop64<2><<<NN / 8, 256>>>(6, 7, 3);      // s1 -> s2
    k_hop64<2><<<NN / 8, 256>>>(7, 8, 3);      // s2 -> s3
    k_tag2<<<NN / 32, 256>>>(tag2_w, tag2_b, lin_w, lin_b, (float*)d_out);
}